// round 5
// baseline (speedup 1.0000x reference)
#include <cuda_runtime.h>
#include <cuda_fp16.h>

// CapsNet dynamic routing — fully register-resident priors.
// x:  [B=256, N=1152, Ci=8]  fp32
// W:  [C=10, N=1152, Ci=8, Co=16] fp32
// out:[C, B, Co] fp32
//
// Prep: W -> fp16 lane-major: Wt[((((c*72+g16)*8+i)*16+nl)*2+h)*8 + j]
//   (n = g16*16+nl, co = 8h+j) so a warp's W load is one contiguous 512B txn.
// Main: block = (c, b-pair). lane = (nl<<1)|h. Each thread computes and HOLDS
// u[(4 slots)][8 co] for both b's in registers; all 3 routing iterations run
// on registers (shfl partner-exchange for logits, 8-value butterfly for s[co],
// h-masked Z) with only ~3KB of SMEM scratch. No u store/load at all.

static constexpr int kB  = 256;
static constexpr int kN  = 1152;
static constexpr int kCi = 8;
static constexpr int kC  = 10;
static constexpr int kCo = 16;
static constexpr int kBT = 2;
static constexpr int kThreads = 576;   // 18 warps
static constexpr int kWarps = 18;
static constexpr int kSlots = 4;       // (n,h) slots per thread: 2304/576

static constexpr int kWTotal = kC * kN * kCi * kCo;   // halfs

__device__ __half g_Wt[kWTotal];

// ---------------- prep: transpose + fp16 convert ---------------------------
__global__ void transpose_W_kernel(const float* __restrict__ W) {
    int o4 = blockIdx.x * blockDim.x + threadIdx.x;    // uint4 (8-half) index
    if (o4 >= kWTotal / 8) return;
    int h   = o4 & 1;
    int nl  = (o4 >> 1) & 15;
    int i   = (o4 >> 5) & 7;
    int cg  = o4 >> 8;                 // c*72 + g16
    int g16 = cg % 72;
    int c   = cg / 72;
    int n   = g16 * 16 + nl;
    const float* src = W + ((size_t)(c * kN + n) * kCi + i) * kCo + h * 8;
    __half2 v[4];
    #pragma unroll
    for (int q = 0; q < 4; ++q)
        v[q] = __floats2half2_rn(src[2 * q], src[2 * q + 1]);
    reinterpret_cast<uint4*>(g_Wt)[o4] = *reinterpret_cast<uint4*>(v);
}

// ---------------- helpers ---------------------------------------------------
// Butterfly reduce of 8 values across the 16 same-h lanes (offsets 2,4,8,16).
// On exit lane holds the warp total for m = b1*4 + b2*2 + b3 (lane bits).
__device__ __forceinline__ float warp_reduce8_h(float a[8], int lane) {
    #pragma unroll
    for (int s = 0; s < 3; ++s) {
        const int off = 2 << s;
        const bool hi = (lane >> (s + 1)) & 1;
        const int hh = 4 >> s;          // 4,2,1
        #pragma unroll
        for (int i = 0; i < hh; ++i) {
            float send = hi ? a[i] : a[i + hh];
            float recv = __shfl_xor_sync(0xFFFFFFFFu, send, off);
            a[i] = (hi ? a[i + hh] : a[i]) + recv;
        }
    }
    return a[0] + __shfl_xor_sync(0xFFFFFFFFu, a[0], 16);
}

// ---------------- main ------------------------------------------------------
__global__ __launch_bounds__(kThreads, 1)
void caps_routing_kernel(const float* __restrict__ x,
                         float* __restrict__ out)
{
    __shared__ float s_red[kBT][kWarps][kCo];
    __shared__ float s_msc[kBT][kWarps];
    __shared__ float s_zsc[kBT][kWarps];
    __shared__ float s_vv[kBT][kCo];

    const int tid  = threadIdx.x;
    const int lane = tid & 31;
    const int wrp  = tid >> 5;           // 0..17
    const int h    = lane & 1;           // co-oct
    const int nl16 = lane >> 1;          // 0..15
    const int c    = blockIdx.y;
    const int b0   = blockIdx.x * kBT;
    // co this lane owns after warp_reduce8_h
    const int mIdx = ((lane >> 1) & 1) * 4 + ((lane >> 2) & 1) * 2 + ((lane >> 3) & 1);
    const int coOwn = h * 8 + mIdx;

    float u0[kSlots][8], u1[kSlots][8];
    float lg0[kSlots], lg1[kSlots];

    // ---------------- Phase 1: priors into registers ----------------------
    {
        const float4* __restrict__ X4  = reinterpret_cast<const float4*>(x);
        const uint4*  __restrict__ Wt4 = reinterpret_cast<const uint4*>(g_Wt);

        #pragma unroll
        for (int k = 0; k < kSlots; ++k) {
            const int n   = k * 288 + wrp * 16 + nl16;
            const int g16 = k * 18 + wrp;

            // my 16B half of each x row (i = 4h..4h+3); partner half via shfl
            float4 xm0 = X4[(b0 * kN + n) * 2 + h];
            float4 xm1 = X4[((b0 + 1) * kN + n) * 2 + h];
            float p00 = __shfl_xor_sync(0xFFFFFFFFu, xm0.x, 1);
            float p01 = __shfl_xor_sync(0xFFFFFFFFu, xm0.y, 1);
            float p02 = __shfl_xor_sync(0xFFFFFFFFu, xm0.z, 1);
            float p03 = __shfl_xor_sync(0xFFFFFFFFu, xm0.w, 1);
            float p10 = __shfl_xor_sync(0xFFFFFFFFu, xm1.x, 1);
            float p11 = __shfl_xor_sync(0xFFFFFFFFu, xm1.y, 1);
            float p12 = __shfl_xor_sync(0xFFFFFFFFu, xm1.z, 1);
            float p13 = __shfl_xor_sync(0xFFFFFFFFu, xm1.w, 1);
            float xv0[8], xv1[8];
            xv0[0] = h ? p00 : xm0.x;  xv0[1] = h ? p01 : xm0.y;
            xv0[2] = h ? p02 : xm0.z;  xv0[3] = h ? p03 : xm0.w;
            xv0[4] = h ? xm0.x : p00;  xv0[5] = h ? xm0.y : p01;
            xv0[6] = h ? xm0.z : p02;  xv0[7] = h ? xm0.w : p03;
            xv1[0] = h ? p10 : xm1.x;  xv1[1] = h ? p11 : xm1.y;
            xv1[2] = h ? p12 : xm1.z;  xv1[3] = h ? p13 : xm1.w;
            xv1[4] = h ? xm1.x : p10;  xv1[5] = h ? xm1.y : p11;
            xv1[6] = h ? xm1.z : p12;  xv1[7] = h ? xm1.w : p13;

            #pragma unroll
            for (int m = 0; m < 8; ++m) { u0[k][m] = 0.f; u1[k][m] = 0.f; }

            // W uint4 index: (((c*72+g16)*8+i)*16 + nl16)*2 + h  (lane-consecutive)
            const size_t wb = ((size_t)((c * 72 + g16) * kCi) * 16 + nl16) * 2 + h;
            #pragma unroll
            for (int i = 0; i < kCi; ++i) {
                uint4 w = Wt4[wb + (size_t)i * 32];
                const __half2* hp = reinterpret_cast<const __half2*>(&w);
                const float xi0 = xv0[i], xi1 = xv1[i];
                #pragma unroll
                for (int q = 0; q < 4; ++q) {
                    float2 f = __half22float2(hp[q]);
                    u0[k][2*q]   += xi0 * f.x;  u0[k][2*q+1] += xi0 * f.y;
                    u1[k][2*q]   += xi1 * f.x;  u1[k][2*q+1] += xi1 * f.y;
                }
            }
        }
    }

    // ---------------- Phase 2: routing (all in registers) ------------------
    // ---- iteration 0: uniform probs ----
    {
        float r[8];
        #pragma unroll
        for (int b = 0; b < 2; ++b) {
            #pragma unroll
            for (int m = 0; m < 8; ++m)
                r[m] = b ? (u1[0][m] + u1[1][m] + u1[2][m] + u1[3][m])
                         : (u0[0][m] + u0[1][m] + u0[2][m] + u0[3][m]);
            float tot = warp_reduce8_h(r, lane);
            if (lane < 16) s_red[b][wrp][coOwn] = tot;
        }
        __syncthreads();

        if (tid < 32) {
            const int b = tid >> 4, co = tid & 15;
            float s = 0.f;
            #pragma unroll
            for (int w = 0; w < kWarps; ++w) s += s_red[b][w][co];
            s *= (1.0f / kN);
            float sq = s * s;
            #pragma unroll
            for (int off = 8; off; off >>= 1)
                sq += __shfl_xor_sync(0xFFFFFFFFu, sq, off);
            s_vv[b][co] = s * sqrtf(sq) / (1.0f + sq);
        }
        __syncthreads();

        float v0[8], v1[8];
        #pragma unroll
        for (int m = 0; m < 8; ++m) {
            v0[m] = s_vv[0][h * 8 + m];
            v1[m] = s_vv[1][h * 8 + m];
        }
        #pragma unroll
        for (int k = 0; k < kSlots; ++k) {
            float d0 = 0.f, d1 = 0.f;
            #pragma unroll
            for (int m = 0; m < 8; ++m) {
                d0 += u0[k][m] * v0[m];
                d1 += u1[k][m] * v1[m];
            }
            lg0[k] = d0 + __shfl_xor_sync(0xFFFFFFFFu, d0, 1);
            lg1[k] = d1 + __shfl_xor_sync(0xFFFFFFFFu, d1, 1);
        }
    }

    // ---- iterations 1, 2 ----
    #pragma unroll 1
    for (int it = 1; it < 3; ++it) {
        float m0 = fmaxf(fmaxf(lg0[0], lg0[1]), fmaxf(lg0[2], lg0[3]));
        float m1 = fmaxf(fmaxf(lg1[0], lg1[1]), fmaxf(lg1[2], lg1[3]));
        #pragma unroll
        for (int off = 16; off; off >>= 1) {
            m0 = fmaxf(m0, __shfl_xor_sync(0xFFFFFFFFu, m0, off));
            m1 = fmaxf(m1, __shfl_xor_sync(0xFFFFFFFFu, m1, off));
        }
        if (lane == 0) { s_msc[0][wrp] = m0; s_msc[1][wrp] = m1; }
        __syncthreads();
        float mm0 = s_msc[0][0], mm1 = s_msc[1][0];
        #pragma unroll
        for (int w = 1; w < kWarps; ++w) {
            mm0 = fmaxf(mm0, s_msc[0][w]);
            mm1 = fmaxf(mm1, s_msc[1][w]);
        }

        float e0[kSlots], e1[kSlots];
        float zp0 = 0.f, zp1 = 0.f;
        #pragma unroll
        for (int k = 0; k < kSlots; ++k) {
            e0[k] = __expf(lg0[k] - mm0);  zp0 += e0[k];
            e1[k] = __expf(lg1[k] - mm1);  zp1 += e1[k];
        }
        if (h) { zp0 = 0.f; zp1 = 0.f; }       // h-pairs duplicate logits
        #pragma unroll
        for (int off = 16; off; off >>= 1) {
            zp0 += __shfl_xor_sync(0xFFFFFFFFu, zp0, off);
            zp1 += __shfl_xor_sync(0xFFFFFFFFu, zp1, off);
        }

        float r[8];
        #pragma unroll
        for (int b = 0; b < 2; ++b) {
            #pragma unroll
            for (int m = 0; m < 8; ++m)
                r[m] = b ? (e1[0]*u1[0][m] + e1[1]*u1[1][m] + e1[2]*u1[2][m] + e1[3]*u1[3][m])
                         : (e0[0]*u0[0][m] + e0[1]*u0[1][m] + e0[2]*u0[2][m] + e0[3]*u0[3][m]);
            float tot = warp_reduce8_h(r, lane);
            if (lane < 16) s_red[b][wrp][coOwn] = tot;
        }
        if (lane == 0) { s_zsc[0][wrp] = zp0; s_zsc[1][wrp] = zp1; }
        __syncthreads();

        if (tid < 32) {
            const int b = tid >> 4, co = tid & 15;
            float Z = 0.f, s = 0.f;
            #pragma unroll
            for (int w = 0; w < kWarps; ++w) { Z += s_zsc[b][w]; s += s_red[b][w][co]; }
            s /= Z;
            float sq = s * s;
            #pragma unroll
            for (int off = 8; off; off >>= 1)
                sq += __shfl_xor_sync(0xFFFFFFFFu, sq, off);
            float v = s * sqrtf(sq) / (1.0f + sq);
            s_vv[b][co] = v;
            if (it == 2)
                out[(c * kB + b0 + b) * kCo + co] = v;
        }
        __syncthreads();

        if (it == 1) {
            float v0[8], v1[8];
            #pragma unroll
            for (int m = 0; m < 8; ++m) {
                v0[m] = s_vv[0][h * 8 + m];
                v1[m] = s_vv[1][h * 8 + m];
            }
            #pragma unroll
            for (int k = 0; k < kSlots; ++k) {
                float d0 = 0.f, d1 = 0.f;
                #pragma unroll
                for (int m = 0; m < 8; ++m) {
                    d0 += u0[k][m] * v0[m];
                    d1 += u1[k][m] * v1[m];
                }
                lg0[k] += d0 + __shfl_xor_sync(0xFFFFFFFFu, d0, 1);
                lg1[k] += d1 + __shfl_xor_sync(0xFFFFFFFFu, d1, 1);
            }
        }
    }
}

extern "C" void kernel_launch(void* const* d_in, const int* in_sizes, int n_in,
                              void* d_out, int out_size)
{
    const float* x = (const float*)d_in[0];
    const float* W = (const float*)d_in[1];
    float* out = (float*)d_out;

    const int prep_threads = 256;
    const int prep_blocks = (kWTotal / 8 + prep_threads - 1) / prep_threads;
    transpose_W_kernel<<<prep_blocks, prep_threads>>>(W);

    dim3 grid(kB / kBT, kC);
    caps_routing_kernel<<<grid, kThreads>>>(x, out);
}

// round 6
// speedup vs baseline: 1.0146x; 1.0146x over previous
#include <cuda_runtime.h>
#include <cuda_fp16.h>

// CapsNet dynamic routing — fused, 2 CTAs/SM for phase overlap.
// x:  [B=256, N=1152, Ci=8]  fp32
// W:  [C=10, N=1152, Ci=8, Co=16] fp32
// out:[C, B, Co] fp32
//
// Prep: W -> fp16 lane-major: uint4 index (((c*36+g32)*8+i)*2+h)*32+nl,
//   n = g32*32+nl, co = 8h+j  -> warp W load = one contiguous 512B txn.
// Main: 384-thread CTA (12 warps), BT=2 b per block, launch_bounds(384,2).
// Phase 1 computes u and stores fp16 into two h-planes (16B rows, fully
// conflict-free). Phase 2 routes b0 then b1 sequentially: 3 rows/thread kept
// packed half2 in registers, fp32 math, butterfly shfl reductions, ~1KB scratch.

static constexpr int kB  = 256;
static constexpr int kN  = 1152;
static constexpr int kCi = 8;
static constexpr int kC  = 10;
static constexpr int kCo = 16;
static constexpr int kBT = 2;
static constexpr int kThreads = 384;   // 12 warps
static constexpr int kWarps = 12;
static constexpr int kRows = 3;        // 1152 / 384

static constexpr int kWTotal = kC * kN * kCi * kCo;   // halfs

__device__ __half g_Wt[kWTotal];

struct Smem {
    uint4 u[kBT][2][kN];        // fp16 priors: [b][h][n] -> 8 halfs (co = 8h+j)
    float red[kWarps][kCo];
    float msc[kWarps];
    float zsc[kWarps];
    float vv[kCo];
};

// ---------------- prep: transpose + fp16 convert ---------------------------
__global__ void transpose_W_kernel(const float* __restrict__ W) {
    int o4 = blockIdx.x * blockDim.x + threadIdx.x;    // uint4 (8-half) index
    if (o4 >= kWTotal / 8) return;
    int nl   = o4 & 31;
    int h    = (o4 >> 5) & 1;
    int i    = (o4 >> 6) & 7;
    int rest = o4 >> 9;
    int g32  = rest % 36;
    int c    = rest / 36;
    int n    = g32 * 32 + nl;
    const float* src = W + ((size_t)(c * kN + n) * kCi + i) * kCo + h * 8;
    __half2 v[4];
    #pragma unroll
    for (int q = 0; q < 4; ++q)
        v[q] = __floats2half2_rn(src[2 * q], src[2 * q + 1]);
    reinterpret_cast<uint4*>(g_Wt)[o4] = *reinterpret_cast<uint4*>(v);
}

// ---------------- helpers ---------------------------------------------------
// Butterfly reduction of 16 values across a warp: 15+1 shfls.
// On exit, return of lane l holds the warp total for co = bitrev4(l & 15).
__device__ __forceinline__ float warp_reduce16(float a[kCo], int lane) {
    #pragma unroll
    for (int b = 0; b < 4; ++b) {
        const int off = 1 << b;
        const bool hi = (lane >> b) & 1;
        const int hh = 16 >> (b + 1);        // 8,4,2,1
        #pragma unroll
        for (int i = 0; i < hh; ++i) {
            float send = hi ? a[i] : a[i + hh];
            float recv = __shfl_xor_sync(0xFFFFFFFFu, send, off);
            a[i] = (hi ? a[i + hh] : a[i]) + recv;
        }
    }
    return a[0] + __shfl_xor_sync(0xFFFFFFFFu, a[0], 16);
}

__device__ __forceinline__ int bitrev4(int l) {
    return ((l & 1) << 3) | ((l & 2) << 1) | ((l & 4) >> 1) | ((l & 8) >> 3);
}

// ---------------- main ------------------------------------------------------
__global__ __launch_bounds__(kThreads, 2)
void caps_routing_kernel(const float* __restrict__ x,
                         float* __restrict__ out)
{
    extern __shared__ unsigned char smem_u8[];
    Smem& sm = *reinterpret_cast<Smem*>(smem_u8);

    const int tid  = threadIdx.x;
    const int lane = tid & 31;
    const int wrp  = tid >> 5;           // 0..11
    const int c    = blockIdx.y;
    const int b0   = blockIdx.x * kBT;
    const int corev = bitrev4(lane & 15);

    // ---------------- Phase 1: priors -> fp16 SMEM planes ------------------
    {
        const int h    = wrp & 1;                       // co-oct
        const int ngrp = wrp >> 1;                      // 0..5
        const float4* __restrict__ X4  = reinterpret_cast<const float4*>(x);
        const uint4*  __restrict__ Wt4 = reinterpret_cast<const uint4*>(g_Wt);

        #pragma unroll 1
        for (int p = 0; p < 6; ++p) {
            const int n   = p * 192 + ngrp * 32 + lane;
            const int g32 = p * 6 + ngrp;

            float4 xa0 = X4[(b0 * kN + n) * 2 + 0];
            float4 xb0 = X4[(b0 * kN + n) * 2 + 1];
            float4 xa1 = X4[((b0 + 1) * kN + n) * 2 + 0];
            float4 xb1 = X4[((b0 + 1) * kN + n) * 2 + 1];
            float x0v[8] = {xa0.x, xa0.y, xa0.z, xa0.w, xb0.x, xb0.y, xb0.z, xb0.w};
            float x1v[8] = {xa1.x, xa1.y, xa1.z, xa1.w, xb1.x, xb1.y, xb1.z, xb1.w};

            float a0[8] = {0,0,0,0,0,0,0,0};
            float a1[8] = {0,0,0,0,0,0,0,0};
            // uint4 index: (((c*36+g32)*8+i)*2+h)*32 + lane ; i stride = 64
            const size_t wb = ((size_t)(c * 36 + g32) * 16 + h) * 32 + lane;
            #pragma unroll
            for (int i = 0; i < kCi; ++i) {
                uint4 w = Wt4[wb + (size_t)i * 64];
                const __half2* hp = reinterpret_cast<const __half2*>(&w);
                const float xi0 = x0v[i], xi1 = x1v[i];
                #pragma unroll
                for (int q = 0; q < 4; ++q) {
                    float2 f = __half22float2(hp[q]);
                    a0[2*q]   += xi0 * f.x;  a0[2*q+1] += xi0 * f.y;
                    a1[2*q]   += xi1 * f.x;  a1[2*q+1] += xi1 * f.y;
                }
            }
            __half2 p0[4], p1[4];
            #pragma unroll
            for (int q = 0; q < 4; ++q) {
                p0[q] = __floats2half2_rn(a0[2*q], a0[2*q+1]);
                p1[q] = __floats2half2_rn(a1[2*q], a1[2*q+1]);
            }
            sm.u[0][h][n] = *reinterpret_cast<uint4*>(p0);
            sm.u[1][h][n] = *reinterpret_cast<uint4*>(p1);
        }
    }
    __syncthreads();

    // ---------------- Phase 2: routing, sequential over b ------------------
    #pragma unroll 1
    for (int bb = 0; bb < kBT; ++bb) {
        // this thread's 3 rows, kept packed fp16 (24 regs)
        __half2 u2[kRows][8];
        #pragma unroll
        for (int k = 0; k < kRows; ++k) {
            const int n = tid + k * kThreads;
            uint4 lo = sm.u[bb][0][n];
            uint4 hi = sm.u[bb][1][n];
            const __half2* l2 = reinterpret_cast<const __half2*>(&lo);
            const __half2* h2 = reinterpret_cast<const __half2*>(&hi);
            #pragma unroll
            for (int q = 0; q < 4; ++q) { u2[k][q] = l2[q]; u2[k][4+q] = h2[q]; }
        }

        float lg[kRows];

        // ---- iteration 0: uniform probs ----
        {
            float r[kCo];
            #pragma unroll
            for (int j = 0; j < 8; ++j) {
                float2 f0 = __half22float2(u2[0][j]);
                float2 f1 = __half22float2(u2[1][j]);
                float2 f2 = __half22float2(u2[2][j]);
                r[2*j]   = f0.x + f1.x + f2.x;
                r[2*j+1] = f0.y + f1.y + f2.y;
            }
            float tot = warp_reduce16(r, lane);
            if (lane < 16) sm.red[wrp][corev] = tot;
            __syncthreads();

            if (tid < kCo) {
                float s = 0.f;
                #pragma unroll
                for (int w = 0; w < kWarps; ++w) s += sm.red[w][tid];
                s *= (1.0f / kN);
                float sq = s * s;
                #pragma unroll
                for (int off = 8; off; off >>= 1)
                    sq += __shfl_xor_sync(0x0000FFFFu, sq, off);
                sm.vv[tid] = s * sqrtf(sq) / (1.0f + sq);
            }
            __syncthreads();

            float v[kCo];
            #pragma unroll
            for (int co = 0; co < kCo; ++co) v[co] = sm.vv[co];
            #pragma unroll
            for (int k = 0; k < kRows; ++k) {
                float d = 0.f;
                #pragma unroll
                for (int j = 0; j < 8; ++j) {
                    float2 f = __half22float2(u2[k][j]);
                    d += f.x * v[2*j] + f.y * v[2*j+1];
                }
                lg[k] = d;
            }
        }

        // ---- iterations 1, 2 ----
        #pragma unroll 1
        for (int it = 1; it < 3; ++it) {
            float m = fmaxf(fmaxf(lg[0], lg[1]), lg[2]);
            #pragma unroll
            for (int off = 16; off; off >>= 1)
                m = fmaxf(m, __shfl_xor_sync(0xFFFFFFFFu, m, off));
            if (lane == 0) sm.msc[wrp] = m;
            __syncthreads();
            float mm = sm.msc[0];
            #pragma unroll
            for (int w = 1; w < kWarps; ++w) mm = fmaxf(mm, sm.msc[w]);

            float e[kRows];
            float zp = 0.f;
            #pragma unroll
            for (int k = 0; k < kRows; ++k) {
                e[k] = __expf(lg[k] - mm);
                zp += e[k];
            }
            #pragma unroll
            for (int off = 16; off; off >>= 1)
                zp += __shfl_xor_sync(0xFFFFFFFFu, zp, off);

            float r[kCo];
            #pragma unroll
            for (int j = 0; j < 8; ++j) {
                float2 f0 = __half22float2(u2[0][j]);
                float2 f1 = __half22float2(u2[1][j]);
                float2 f2 = __half22float2(u2[2][j]);
                r[2*j]   = e[0]*f0.x + e[1]*f1.x + e[2]*f2.x;
                r[2*j+1] = e[0]*f0.y + e[1]*f1.y + e[2]*f2.y;
            }
            float tot = warp_reduce16(r, lane);
            if (lane == 0) sm.zsc[wrp] = zp;
            if (lane < 16) sm.red[wrp][corev] = tot;
            __syncthreads();

            if (tid < kCo) {
                float Z = 0.f, s = 0.f;
                #pragma unroll
                for (int w = 0; w < kWarps; ++w) { Z += sm.zsc[w]; s += sm.red[w][tid]; }
                s /= Z;
                float sq = s * s;
                #pragma unroll
                for (int off = 8; off; off >>= 1)
                    sq += __shfl_xor_sync(0x0000FFFFu, sq, off);
                float v = s * sqrtf(sq) / (1.0f + sq);
                sm.vv[tid] = v;
                if (it == 2)
                    out[(c * kB + b0 + bb) * kCo + tid] = v;
            }
            __syncthreads();

            if (it == 1) {
                float v[kCo];
                #pragma unroll
                for (int co = 0; co < kCo; ++co) v[co] = sm.vv[co];
                #pragma unroll
                for (int k = 0; k < kRows; ++k) {
                    float d = 0.f;
                    #pragma unroll
                    for (int j = 0; j < 8; ++j) {
                        float2 f = __half22float2(u2[k][j]);
                        d += f.x * v[2*j] + f.y * v[2*j+1];
                    }
                    lg[k] += d;
                }
            }
        }
    }
}

extern "C" void kernel_launch(void* const* d_in, const int* in_sizes, int n_in,
                              void* d_out, int out_size)
{
    const float* x = (const float*)d_in[0];
    const float* W = (const float*)d_in[1];
    float* out = (float*)d_out;

    const int prep_threads = 256;
    const int prep_blocks = (kWTotal / 8 + prep_threads - 1) / prep_threads;
    transpose_W_kernel<<<prep_blocks, prep_threads>>>(W);

    cudaFuncSetAttribute(caps_routing_kernel,
                         cudaFuncAttributeMaxDynamicSharedMemorySize,
                         (int)sizeof(Smem));
    dim3 grid(kB / kBT, kC);
    caps_routing_kernel<<<grid, kThreads, sizeof(Smem)>>>(x, out);
}

// round 7
// speedup vs baseline: 1.2766x; 1.2582x over previous
#include <cuda_runtime.h>
#include <cuda_fp16.h>

// CapsNet dynamic routing — fused, 2 CTAs/SM for phase overlap.
// x:  [B=256, N=1152, Ci=8]  fp32
// W:  [C=10, N=1152, Ci=8, Co=16] fp32
// out:[C, B, Co] fp32
//
// Prep (SMEM transpose, coalesced both sides): W -> fp16 lane-major,
//   uint4 index (((c*36+g32)*8+i)*2+h)*32+nl,  n = g32*32+nl, co = 8h+j
//   -> main-kernel warp W load = one contiguous 512B txn.
// Main: 384-thread CTA (12 warps), BT=2 b per block, launch_bounds(384,2).
// Phase 1 computes u with packed fma.rn.f32x2 accumulation and stores fp16
// into two h-planes (16B rows, conflict-free). Phase 2 routes b0 then b1:
// 3 rows/thread packed half2 in registers, fp32 math, butterfly reductions.

static constexpr int kB  = 256;
static constexpr int kN  = 1152;
static constexpr int kCi = 8;
static constexpr int kC  = 10;
static constexpr int kCo = 16;
static constexpr int kBT = 2;
static constexpr int kThreads = 384;   // 12 warps
static constexpr int kWarps = 12;
static constexpr int kRows = 3;        // 1152 / 384

static constexpr int kWTotal = kC * kN * kCi * kCo;   // halfs

__device__ __half g_Wt[kWTotal];

struct Smem {
    uint4 u[kBT][2][kN];        // fp16 priors: [b][h][n] -> 8 halfs (co = 8h+j)
    float red[kWarps][kCo];
    float msc[kWarps];
    float zsc[kWarps];
    float vv[kCo];
};

// ---------------- packed f32x2 helpers --------------------------------------
__device__ __forceinline__ unsigned long long pk2(float a, float b) {
    unsigned long long r;
    asm("mov.b64 %0, {%1, %2};" : "=l"(r) : "f"(a), "f"(b));
    return r;
}
__device__ __forceinline__ unsigned long long fma2(unsigned long long a,
                                                   unsigned long long b,
                                                   unsigned long long c) {
    unsigned long long d;
    asm("fma.rn.f32x2 %0, %1, %2, %3;" : "=l"(d) : "l"(a), "l"(b), "l"(c));
    return d;
}
__device__ __forceinline__ float2 upk2(unsigned long long a) {
    float x, y;
    asm("mov.b64 {%0, %1}, %2;" : "=f"(x), "=f"(y) : "l"(a));
    return make_float2(x, y);
}

// ---------------- prep: coalesced SMEM-transpose + fp16 convert -------------
// block = one (c, g32) chunk: 32n x 8i x 16co = 16KB fp32 in, 8KB fp16 out.
__global__ __launch_bounds__(256)
void transpose_W_kernel(const float* __restrict__ W) {
    __shared__ __half s[32][136];          // 128 halfs/row + 8 pad (272B rows)
    const int blk = blockIdx.x;            // c*36 + g32
    const int tid = threadIdx.x;

    const float4* src = reinterpret_cast<const float4*>(W) + (size_t)blk * 1024;
    #pragma unroll
    for (int q = 0; q < 4; ++q) {
        const int v  = tid + q * 256;      // float4 idx 0..1023 (coalesced)
        float4 f = src[v];
        const int nl  = v >> 5;            // 32 float4 per n-row
        const int col = (v & 31) * 4;      // half column
        __half2 h01 = __floats2half2_rn(f.x, f.y);
        __half2 h23 = __floats2half2_rn(f.z, f.w);
        *reinterpret_cast<__half2*>(&s[nl][col])     = h01;
        *reinterpret_cast<__half2*>(&s[nl][col + 2]) = h23;
    }
    __syncthreads();

    uint4* dst = reinterpret_cast<uint4*>(g_Wt) + (size_t)blk * 512;
    #pragma unroll
    for (int q = 0; q < 2; ++q) {
        const int o  = tid + q * 256;      // 0..511
        const int nl = o & 31;
        const int ih = o >> 5;             // i*2 + h
        dst[o] = *reinterpret_cast<const uint4*>(&s[nl][ih * 8]);  // 16B aligned
    }
}

// ---------------- helpers ----------------------------------------------------
// Butterfly reduction of 16 values across a warp: 15+1 shfls.
// On exit, return of lane l holds the warp total for co = bitrev4(l & 15).
__device__ __forceinline__ float warp_reduce16(float a[kCo], int lane) {
    #pragma unroll
    for (int b = 0; b < 4; ++b) {
        const int off = 1 << b;
        const bool hi = (lane >> b) & 1;
        const int hh = 16 >> (b + 1);        // 8,4,2,1
        #pragma unroll
        for (int i = 0; i < hh; ++i) {
            float send = hi ? a[i] : a[i + hh];
            float recv = __shfl_xor_sync(0xFFFFFFFFu, send, off);
            a[i] = (hi ? a[i + hh] : a[i]) + recv;
        }
    }
    return a[0] + __shfl_xor_sync(0xFFFFFFFFu, a[0], 16);
}

__device__ __forceinline__ int bitrev4(int l) {
    return ((l & 1) << 3) | ((l & 2) << 1) | ((l & 4) >> 1) | ((l & 8) >> 3);
}

// ---------------- main --------------------------------------------------------
__global__ __launch_bounds__(kThreads, 2)
void caps_routing_kernel(const float* __restrict__ x,
                         float* __restrict__ out)
{
    extern __shared__ unsigned char smem_u8[];
    Smem& sm = *reinterpret_cast<Smem*>(smem_u8);

    const int tid  = threadIdx.x;
    const int lane = tid & 31;
    const int wrp  = tid >> 5;           // 0..11
    const int c    = blockIdx.y;
    const int b0   = blockIdx.x * kBT;
    const int corev = bitrev4(lane & 15);

    // ---------------- Phase 1: priors -> fp16 SMEM planes ------------------
    {
        const int h    = wrp & 1;                       // co-oct
        const int ngrp = wrp >> 1;                      // 0..5
        const float4* __restrict__ X4  = reinterpret_cast<const float4*>(x);
        const uint4*  __restrict__ Wt4 = reinterpret_cast<const uint4*>(g_Wt);

        #pragma unroll 1
        for (int p = 0; p < 6; ++p) {
            const int n   = p * 192 + ngrp * 32 + lane;
            const int g32 = p * 6 + ngrp;

            float4 xa0 = X4[(b0 * kN + n) * 2 + 0];
            float4 xb0 = X4[(b0 * kN + n) * 2 + 1];
            float4 xa1 = X4[((b0 + 1) * kN + n) * 2 + 0];
            float4 xb1 = X4[((b0 + 1) * kN + n) * 2 + 1];
            float x0v[8] = {xa0.x, xa0.y, xa0.z, xa0.w, xb0.x, xb0.y, xb0.z, xb0.w};
            float x1v[8] = {xa1.x, xa1.y, xa1.z, xa1.w, xb1.x, xb1.y, xb1.z, xb1.w};

            unsigned long long acc0[4] = {0ull, 0ull, 0ull, 0ull};
            unsigned long long acc1[4] = {0ull, 0ull, 0ull, 0ull};
            // uint4 index: (((c*36+g32)*8+i)*2+h)*32 + lane ; i stride = 64
            const size_t wb = ((size_t)(c * 36 + g32) * 16 + h) * 32 + lane;
            #pragma unroll
            for (int i = 0; i < kCi; ++i) {
                uint4 w = Wt4[wb + (size_t)i * 64];
                const __half2* hp = reinterpret_cast<const __half2*>(&w);
                const unsigned long long xi0 = pk2(x0v[i], x0v[i]);
                const unsigned long long xi1 = pk2(x1v[i], x1v[i]);
                #pragma unroll
                for (int q = 0; q < 4; ++q) {
                    float2 f = __half22float2(hp[q]);
                    unsigned long long wp = pk2(f.x, f.y);
                    acc0[q] = fma2(xi0, wp, acc0[q]);
                    acc1[q] = fma2(xi1, wp, acc1[q]);
                }
            }
            __half2 p0[4], p1[4];
            #pragma unroll
            for (int q = 0; q < 4; ++q) {
                float2 f0 = upk2(acc0[q]);
                float2 f1 = upk2(acc1[q]);
                p0[q] = __floats2half2_rn(f0.x, f0.y);
                p1[q] = __floats2half2_rn(f1.x, f1.y);
            }
            sm.u[0][h][n] = *reinterpret_cast<uint4*>(p0);
            sm.u[1][h][n] = *reinterpret_cast<uint4*>(p1);
        }
    }
    __syncthreads();

    // ---------------- Phase 2: routing, sequential over b ------------------
    #pragma unroll 1
    for (int bb = 0; bb < kBT; ++bb) {
        // this thread's 3 rows, kept packed fp16 (24 regs)
        __half2 u2[kRows][8];
        #pragma unroll
        for (int k = 0; k < kRows; ++k) {
            const int n = tid + k * kThreads;
            uint4 lo = sm.u[bb][0][n];
            uint4 hi = sm.u[bb][1][n];
            const __half2* l2 = reinterpret_cast<const __half2*>(&lo);
            const __half2* h2 = reinterpret_cast<const __half2*>(&hi);
            #pragma unroll
            for (int q = 0; q < 4; ++q) { u2[k][q] = l2[q]; u2[k][4+q] = h2[q]; }
        }

        float lg[kRows];

        // ---- iteration 0: uniform probs ----
        {
            float r[kCo];
            #pragma unroll
            for (int j = 0; j < 8; ++j) {
                float2 f0 = __half22float2(u2[0][j]);
                float2 f1 = __half22float2(u2[1][j]);
                float2 f2 = __half22float2(u2[2][j]);
                r[2*j]   = f0.x + f1.x + f2.x;
                r[2*j+1] = f0.y + f1.y + f2.y;
            }
            float tot = warp_reduce16(r, lane);
            if (lane < 16) sm.red[wrp][corev] = tot;
            __syncthreads();

            if (tid < kCo) {
                float s = 0.f;
                #pragma unroll
                for (int w = 0; w < kWarps; ++w) s += sm.red[w][tid];
                s *= (1.0f / kN);
                float sq = s * s;
                #pragma unroll
                for (int off = 8; off; off >>= 1)
                    sq += __shfl_xor_sync(0x0000FFFFu, sq, off);
                sm.vv[tid] = s * sqrtf(sq) / (1.0f + sq);
            }
            __syncthreads();

            float v[kCo];
            #pragma unroll
            for (int co = 0; co < kCo; ++co) v[co] = sm.vv[co];
            #pragma unroll
            for (int k = 0; k < kRows; ++k) {
                float d = 0.f;
                #pragma unroll
                for (int j = 0; j < 8; ++j) {
                    float2 f = __half22float2(u2[k][j]);
                    d += f.x * v[2*j] + f.y * v[2*j+1];
                }
                lg[k] = d;
            }
        }

        // ---- iterations 1, 2 ----
        #pragma unroll 1
        for (int it = 1; it < 3; ++it) {
            float m = fmaxf(fmaxf(lg[0], lg[1]), lg[2]);
            #pragma unroll
            for (int off = 16; off; off >>= 1)
                m = fmaxf(m, __shfl_xor_sync(0xFFFFFFFFu, m, off));
            if (lane == 0) sm.msc[wrp] = m;
            __syncthreads();
            float mm = sm.msc[0];
            #pragma unroll
            for (int w = 1; w < kWarps; ++w) mm = fmaxf(mm, sm.msc[w]);

            float e[kRows];
            float zp = 0.f;
            #pragma unroll
            for (int k = 0; k < kRows; ++k) {
                e[k] = __expf(lg[k] - mm);
                zp += e[k];
            }
            #pragma unroll
            for (int off = 16; off; off >>= 1)
                zp += __shfl_xor_sync(0xFFFFFFFFu, zp, off);

            float r[kCo];
            #pragma unroll
            for (int j = 0; j < 8; ++j) {
                float2 f0 = __half22float2(u2[0][j]);
                float2 f1 = __half22float2(u2[1][j]);
                float2 f2 = __half22float2(u2[2][j]);
                r[2*j]   = e[0]*f0.x + e[1]*f1.x + e[2]*f2.x;
                r[2*j+1] = e[0]*f0.y + e[1]*f1.y + e[2]*f2.y;
            }
            float tot = warp_reduce16(r, lane);
            if (lane == 0) sm.zsc[wrp] = zp;
            if (lane < 16) sm.red[wrp][corev] = tot;
            __syncthreads();

            if (tid < kCo) {
                float Z = 0.f, s = 0.f;
                #pragma unroll
                for (int w = 0; w < kWarps; ++w) { Z += sm.zsc[w]; s += sm.red[w][tid]; }
                s /= Z;
                float sq = s * s;
                #pragma unroll
                for (int off = 8; off; off >>= 1)
                    sq += __shfl_xor_sync(0x0000FFFFu, sq, off);
                float v = s * sqrtf(sq) / (1.0f + sq);
                sm.vv[tid] = v;
                if (it == 2)
                    out[(c * kB + b0 + bb) * kCo + tid] = v;
            }
            __syncthreads();

            if (it == 1) {
                float v[kCo];
                #pragma unroll
                for (int co = 0; co < kCo; ++co) v[co] = sm.vv[co];
                #pragma unroll
                for (int k = 0; k < kRows; ++k) {
                    float d = 0.f;
                    #pragma unroll
                    for (int j = 0; j < 8; ++j) {
                        float2 f = __half22float2(u2[k][j]);
                        d += f.x * v[2*j] + f.y * v[2*j+1];
                    }
                    lg[k] += d;
                }
            }
        }
    }
}

extern "C" void kernel_launch(void* const* d_in, const int* in_sizes, int n_in,
                              void* d_out, int out_size)
{
    const float* x = (const float*)d_in[0];
    const float* W = (const float*)d_in[1];
    float* out = (float*)d_out;

    transpose_W_kernel<<<kC * 36, 256>>>(W);

    cudaFuncSetAttribute(caps_routing_kernel,
                         cudaFuncAttributeMaxDynamicSharedMemorySize,
                         (int)sizeof(Smem));
    dim3 grid(kB / kBT, kC);
    caps_routing_kernel<<<grid, kThreads, sizeof(Smem)>>>(x, out);
}